// round 1
// baseline (speedup 1.0000x reference)
#include <cuda_runtime.h>
#include <math.h>

#define NN 50000
#define NE 800000

// ---------------- scratch (static device globals; no allocation) ----------------
__device__ int   g_is64;
__device__ int   g_deg[NN];
__device__ int   g_off[NN + 1];
__device__ int   g_cur[NN];
__device__ int   g_csr[NE];
__device__ float g_amp[NN];
__device__ float g_att[NN];
__device__ float g_P[NN * 128];
__device__ float g_Q[NN * 128];
__device__ float g_agg[NN * 384];
__device__ float g_h1[NN * 128];
__device__ float g_h2[NN * 128];

// ---------------- index-width detection (int32 vs int64 indices) ----------------
__global__ void detect_kernel(const void* dst, int e, int n) {
    // One block. Interpret as int64: if any of the first K entries is out of
    // [0, n), the buffer is int32 (two packed 32-bit values look huge).
    __shared__ int bad;
    if (threadIdx.x == 0) bad = 0;
    __syncthreads();
    int k = e < 1024 ? e : 1024;
    const long long* p = (const long long*)dst;
    for (int i = threadIdx.x; i < k; i += blockDim.x) {
        long long v = p[i];
        if (v < 0 || v >= (long long)n) atomicExch(&bad, 1);
    }
    __syncthreads();
    if (threadIdx.x == 0) g_is64 = bad ? 0 : 1;
}

__device__ __forceinline__ int load_idx(const void* p, int i) {
    if (g_is64) return (int)((const long long*)p)[i];
    return ((const int*)p)[i];
}

// ---------------- CSR build ----------------
__global__ void zero_deg(int n) {
    int i = blockIdx.x * blockDim.x + threadIdx.x;
    if (i < n) g_deg[i] = 0;
}

__global__ void hist_kernel(const void* __restrict__ dst, int e) {
    int i = blockIdx.x * blockDim.x + threadIdx.x;
    if (i < e) atomicAdd(&g_deg[load_idx(dst, i)], 1);
}

__global__ void scan_kernel(int n) {
    // single block, 1024 threads: chunked Hillis-Steele inclusive scan
    __shared__ int temp[1024];
    __shared__ int carry;
    int tid = threadIdx.x;
    if (tid == 0) carry = 0;
    __syncthreads();
    for (int base = 0; base < n; base += 1024) {
        int i = base + tid;
        int v = (i < n) ? g_deg[i] : 0;
        temp[tid] = v;
        __syncthreads();
        #pragma unroll
        for (int off = 1; off < 1024; off <<= 1) {
            int t = (tid >= off) ? temp[tid - off] : 0;
            __syncthreads();
            temp[tid] += t;
            __syncthreads();
        }
        int incl = temp[tid] + carry;
        if (i < n) {
            int excl = incl - v;
            g_off[i] = excl;
            g_cur[i] = excl;
            float d  = (float)v;
            float ld = logf(d + 1.0f);
            g_amp[i] = ld * (1.0f / 3.0f);
            g_att[i] = 3.0f / fmaxf(ld, 1e-6f);
        }
        __syncthreads();
        if (tid == 0) carry += temp[1023];
        __syncthreads();
    }
    if (tid == 0) g_off[n] = carry;
}

__global__ void scatter_kernel(const void* __restrict__ src,
                               const void* __restrict__ dst, int e) {
    int i = blockIdx.x * blockDim.x + threadIdx.x;
    if (i < e) {
        int d   = load_idx(dst, i);
        int pos = atomicAdd(&g_cur[d], 1);
        g_csr[pos] = load_idx(src, i);
    }
}

// ---------------- input selection helper ----------------
template <int SEL>
__device__ __forceinline__ const float* sel_in(const float* a) {
    if constexpr (SEL == 1) return g_h1;
    else if constexpr (SEL == 2) return g_h2;
    else return a;
}

// ---------------- P/Q GEMM: C[MxN=128] = A[Mx128] @ B[128x128] (+bias on Q) ----------------
template <int INSEL, bool QSIDE>
__global__ __launch_bounds__(256) void sgemm_pq(const float* __restrict__ hin,
                                                const float* __restrict__ Mw,
                                                const float* __restrict__ Mb,
                                                int M) {
    const float* A = sel_in<INSEL>(hin);
    const float* B = Mw + (QSIDE ? 128 * 128 : 0);
    float* C       = QSIDE ? g_Q : g_P;

    __shared__ float As[16][132];
    __shared__ float Bs[16][128];

    int tid  = threadIdx.x;
    int ty   = tid >> 4, tx = tid & 15;
    int row0 = blockIdx.x * 128;
    float acc[8][8] = {};
    int rA = tid >> 2, cA = (tid & 3) << 2;
    int rB = tid >> 5, cB = (tid & 31) << 2;

    for (int k0 = 0; k0 < 128; k0 += 16) {
        #pragma unroll
        for (int p = 0; p < 2; p++) {
            int gr = row0 + rA + p * 64;
            float4 v = make_float4(0.f, 0.f, 0.f, 0.f);
            if (gr < M) v = *(const float4*)(A + (long)gr * 128 + k0 + cA);
            As[cA + 0][rA + p * 64] = v.x;
            As[cA + 1][rA + p * 64] = v.y;
            As[cA + 2][rA + p * 64] = v.z;
            As[cA + 3][rA + p * 64] = v.w;
        }
        #pragma unroll
        for (int p = 0; p < 2; p++) {
            *(float4*)&Bs[rB + p * 8][cB] =
                *(const float4*)(B + (k0 + rB + p * 8) * 128 + cB);
        }
        __syncthreads();
        #pragma unroll
        for (int kk = 0; kk < 16; kk++) {
            float a[8], b[8];
            #pragma unroll
            for (int m = 0; m < 8; m++) a[m] = As[kk][ty * 8 + m];
            #pragma unroll
            for (int nn = 0; nn < 8; nn++) b[nn] = Bs[kk][tx * 8 + nn];
            #pragma unroll
            for (int m = 0; m < 8; m++)
                #pragma unroll
                for (int nn = 0; nn < 8; nn++)
                    acc[m][nn] = fmaf(a[m], b[nn], acc[m][nn]);
        }
        __syncthreads();
    }
    #pragma unroll
    for (int m = 0; m < 8; m++) {
        int gr = row0 + ty * 8 + m;
        if (gr < M) {
            #pragma unroll
            for (int nn = 0; nn < 8; nn++) {
                int gc  = tx * 8 + nn;
                float v = acc[m][nn];
                if (QSIDE) v += Mb[gc];
                C[(long)gr * 128 + gc] = v;
            }
        }
    }
}

// ---------------- CSR aggregation: warp per node, float4 per lane ----------------
__global__ void agg_kernel(int n) {
    int gw   = (blockIdx.x * blockDim.x + threadIdx.x) >> 5;
    int lane = threadIdx.x & 31;
    if (gw >= n) return;
    int s = g_off[gw], e = g_off[gw + 1];
    int c = lane * 4;
    float4 sum = make_float4(0.f, 0.f, 0.f, 0.f);
    float4 mn  = make_float4(1e30f, 1e30f, 1e30f, 1e30f);
    float4 mx  = make_float4(-1e30f, -1e30f, -1e30f, -1e30f);
    for (int i = s; i < e; i++) {
        int r    = g_csr[i];
        float4 v = *(const float4*)&g_P[(long)r * 128 + c];
        sum.x += v.x; sum.y += v.y; sum.z += v.z; sum.w += v.w;
        mn.x = fminf(mn.x, v.x); mn.y = fminf(mn.y, v.y);
        mn.z = fminf(mn.z, v.z); mn.w = fminf(mn.w, v.w);
        mx.x = fmaxf(mx.x, v.x); mx.y = fmaxf(mx.y, v.y);
        mx.z = fmaxf(mx.z, v.z); mx.w = fmaxf(mx.w, v.w);
    }
    float4 q = *(const float4*)&g_Q[(long)gw * 128 + c];
    float4 me, on, ox;
    int d = e - s;
    if (d > 0) {
        float inv = 1.0f / (float)d;
        me.x = sum.x * inv + q.x; me.y = sum.y * inv + q.y;
        me.z = sum.z * inv + q.z; me.w = sum.w * inv + q.w;
        on.x = mn.x + q.x; on.y = mn.y + q.y; on.z = mn.z + q.z; on.w = mn.w + q.w;
        ox.x = mx.x + q.x; ox.y = mx.y + q.y; ox.z = mx.z + q.z; ox.w = mx.w + q.w;
    } else {
        me = make_float4(0.f, 0.f, 0.f, 0.f);
        on = me; ox = me;
    }
    *(float4*)&g_agg[(long)gw * 384 + c]       = me;
    *(float4*)&g_agg[(long)gw * 384 + 128 + c] = on;
    *(float4*)&g_agg[(long)gw * 384 + 256 + c] = ox;
}

// ---------------- fused update GEMM ----------------
// C[M x BN] = [ h | agg | agg*amp | agg*att ] (M x 1280) @ Uw (1280 x BN) + Ub
// A is synthesized in the tile loader (region select + per-row scale).
template <int INSEL, int OUTSEL, int BN, int TN, bool RELU>
__global__ __launch_bounds__(256) void sgemm_update(const float* __restrict__ hin,
                                                    const float* __restrict__ Uw,
                                                    const float* __restrict__ Ub,
                                                    float* __restrict__ outp,
                                                    int M) {
    const float* H = sel_in<INSEL>(hin);
    float* C;
    if constexpr (OUTSEL == 1) C = g_h1;
    else if constexpr (OUTSEL == 2) C = g_h2;
    else C = outp;

    constexpr int TM = 8, BK = 16, BM = 128;
    constexpr int TXN = BN / TN;
    __shared__ float As[BK][BM + 4];
    __shared__ float Bs[BK][BN];

    int tid  = threadIdx.x;
    int ty   = tid / TXN, tx = tid % TXN;
    int row0 = blockIdx.x * BM;
    float acc[TM][TN] = {};
    int rA = tid >> 2, cA = (tid & 3) << 2;
    constexpr int QPR = BN / 4;     // float4 slots per B row
    constexpr int RPP = 256 / QPR;  // B rows loaded per pass
    int rB = tid / QPR, cB = (tid % QPR) * 4;

    for (int kt = 0; kt < 80; kt++) {
        int k0 = kt * 16;
        #pragma unroll
        for (int p = 0; p < 2; p++) {
            int gr = row0 + rA + p * 64;
            float4 v = make_float4(0.f, 0.f, 0.f, 0.f);
            if (gr < M) {
                if (k0 < 128) {
                    v = *(const float4*)(H + (long)gr * 128 + k0 + cA);
                } else {
                    int koff; float s;
                    if (k0 < 512)      { koff = k0 - 128; s = 1.0f; }
                    else if (k0 < 896) { koff = k0 - 512; s = g_amp[gr]; }
                    else               { koff = k0 - 896; s = g_att[gr]; }
                    v = *(const float4*)(g_agg + (long)gr * 384 + koff + cA);
                    v.x *= s; v.y *= s; v.z *= s; v.w *= s;
                }
            }
            As[cA + 0][rA + p * 64] = v.x;
            As[cA + 1][rA + p * 64] = v.y;
            As[cA + 2][rA + p * 64] = v.z;
            As[cA + 3][rA + p * 64] = v.w;
        }
        #pragma unroll
        for (int p = 0; p < BK / RPP; p++) {
            *(float4*)&Bs[rB + p * RPP][cB] =
                *(const float4*)(Uw + (long)(k0 + rB + p * RPP) * BN + cB);
        }
        __syncthreads();
        #pragma unroll
        for (int kk = 0; kk < BK; kk++) {
            float a[TM], b[TN];
            #pragma unroll
            for (int m = 0; m < TM; m++) a[m] = As[kk][ty * TM + m];
            #pragma unroll
            for (int nn = 0; nn < TN; nn++) b[nn] = Bs[kk][tx * TN + nn];
            #pragma unroll
            for (int m = 0; m < TM; m++)
                #pragma unroll
                for (int nn = 0; nn < TN; nn++)
                    acc[m][nn] = fmaf(a[m], b[nn], acc[m][nn]);
        }
        __syncthreads();
    }
    #pragma unroll
    for (int m = 0; m < TM; m++) {
        int gr = row0 + ty * TM + m;
        if (gr < M) {
            #pragma unroll
            for (int nn = 0; nn < TN; nn++) {
                int gc  = tx * TN + nn;
                float v = acc[m][nn] + Ub[gc];
                if (RELU) v = fmaxf(v, 0.0f);
                C[(long)gr * BN + gc] = v;
            }
        }
    }
}

// ---------------- host launcher ----------------
extern "C" void kernel_launch(void* const* d_in, const int* in_sizes, int n_in,
                              void* d_out, int out_size) {
    const float* x   = (const float*)d_in[0];
    const void*  src = d_in[1];
    const void*  dst = d_in[2];
    const float* M0w = (const float*)d_in[3];
    const float* M0b = (const float*)d_in[4];
    const float* U0w = (const float*)d_in[5];
    const float* U0b = (const float*)d_in[6];
    const float* M1w = (const float*)d_in[7];
    const float* M1b = (const float*)d_in[8];
    const float* U1w = (const float*)d_in[9];
    const float* U1b = (const float*)d_in[10];
    const float* M2w = (const float*)d_in[11];
    const float* M2b = (const float*)d_in[12];
    const float* U2w = (const float*)d_in[13];
    const float* U2b = (const float*)d_in[14];

    int n = in_sizes[0] / 128;
    int e = in_sizes[1];
    if (n > NN) n = NN;
    if (e > NE) e = NE;

    int gE = (e + 255) / 256;
    int gN = (n + 255) / 256;
    int gM = (n + 127) / 128;
    int gA = (n * 32 + 255) / 256;

    // CSR build + node scalars
    detect_kernel<<<1, 256>>>(dst, e, n);
    zero_deg<<<gN, 256>>>(n);
    hist_kernel<<<gE, 256>>>(dst, e);
    scan_kernel<<<1, 1024>>>(n);
    scatter_kernel<<<gE, 256>>>(src, dst, e);

    // layer 0: in = x, out = g_h1
    sgemm_pq<0, false><<<gM, 256>>>(x, M0w, nullptr, n);
    sgemm_pq<0, true ><<<gM, 256>>>(x, M0w, M0b, n);
    agg_kernel<<<gA, 256>>>(n);
    sgemm_update<0, 1, 128, 8, true><<<gM, 256>>>(x, U0w, U0b, nullptr, n);

    // layer 1: in = g_h1, out = g_h2
    sgemm_pq<1, false><<<gM, 256>>>(nullptr, M1w, nullptr, n);
    sgemm_pq<1, true ><<<gM, 256>>>(nullptr, M1w, M1b, n);
    agg_kernel<<<gA, 256>>>(n);
    sgemm_update<1, 2, 128, 8, true><<<gM, 256>>>(nullptr, U1w, U1b, nullptr, n);

    // layer 2: in = g_h2, out = d_out (N=64, no relu)
    sgemm_pq<2, false><<<gM, 256>>>(nullptr, M2w, nullptr, n);
    sgemm_pq<2, true ><<<gM, 256>>>(nullptr, M2w, M2b, n);
    agg_kernel<<<gA, 256>>>(n);
    sgemm_update<2, 0, 64, 4, false><<<gM, 256>>>(nullptr, U2w, U2b,
                                                  (float*)d_out, n);
}